// round 10
// baseline (speedup 1.0000x reference)
#include <cuda_runtime.h>
#include <cuda_fp16.h>
#include <cuda_bf16.h>
#include <mma.h>
#include <math.h>

using namespace nvcuda;

#define N_USERS 100000
#define N_ITEMS 50000
#define N_NODES 150000
#define EMB 64
#define NINT 128
#define MAX_EDGES 4000000

#define N4 ((N_NODES + 3) / 4)
#define NBLK ((N4 + 1023) / 1024)

// ---------------- static device scratch ----------------
__device__ int    g_deg[N_NODES];
__device__ float  g_dis[N_NODES];
__device__ int    g_rowptr[N_NODES + 1];
__device__ int    g_cursor[N_NODES];
__device__ int    g_ecol[MAX_EDGES];
__device__ volatile unsigned long long g_state[NBLK];
__device__ float  g_embA[(size_t)N_NODES * EMB];
__device__ float  g_embB[(size_t)N_NODES * EMB];
__device__ __half g_embS[(size_t)N_NODES * EMB];   // dis-scaled spmm input (fp16)

// ---------------- packed fp32x2 helpers ----------------
__device__ __forceinline__ unsigned long long fma2(unsigned long long a,
                                                   unsigned long long b,
                                                   unsigned long long c) {
    unsigned long long d;
    asm("fma.rn.f32x2 %0, %1, %2, %3;" : "=l"(d) : "l"(a), "l"(b), "l"(c));
    return d;
}
__device__ __forceinline__ unsigned long long pk2(float x, float y) {
    unsigned long long r;
    asm("mov.b64 %0, {%1, %2};" : "=l"(r) : "f"(x), "f"(y));
    return r;
}
__device__ __forceinline__ float2 upk(unsigned long long v) {
    float2 f;
    asm("mov.b64 {%0, %1}, %2;" : "=f"(f.x), "=f"(f.y) : "l"(v));
    return f;
}
__device__ __forceinline__ unsigned long long h2f2(unsigned int h) {
    float2 f = __half22float2(*(const __half2*)&h);
    return pk2(f.x, f.y);
}

// ---------------- precompute ----------------
__global__ void hist_kernel(const int* __restrict__ h, int n) {
    int stride = gridDim.x * blockDim.x;
    for (int i = blockIdx.x * blockDim.x + threadIdx.x; i < n; i += stride)
        atomicAdd(&g_deg[h[i]], 1);
}

__global__ __launch_bounds__(1024) void scan_kernel(int n_edges) {
    __shared__ int ws[32];
    __shared__ int s_excl;
    const int t = threadIdx.x, b = blockIdx.x;
    const int lane = t & 31, wid = t >> 5;
    const int idx = b * 1024 + t;
    int4 v = (idx < N4) ? ((const int4*)g_deg)[idx] : make_int4(0, 0, 0, 0);
    int s = v.x + v.y + v.z + v.w;
    int x = s;
    #pragma unroll
    for (int o = 1; o < 32; o <<= 1) {
        int y = __shfl_up_sync(0xffffffffu, x, o);
        if (lane >= o) x += y;
    }
    if (lane == 31) ws[wid] = x;
    __syncthreads();
    if (wid == 0) {
        int z = ws[lane];
        #pragma unroll
        for (int o = 1; o < 32; o <<= 1) {
            int y = __shfl_up_sync(0xffffffffu, z, o);
            if (lane >= o) z += y;
        }
        ws[lane] = z;
    }
    __syncthreads();
    const int total = ws[31];

    if (t == 0) {
        if (b == 0) {
            g_state[0] = (2ull << 32) | (unsigned)total;
            s_excl = 0;
        } else {
            g_state[b] = (1ull << 32) | (unsigned)total;
            int excl = 0;
            int p = b - 1;
            while (true) {
                unsigned long long st;
                do { st = g_state[p]; } while ((st >> 32) == 0ull);
                excl += (int)(unsigned)st;
                if ((st >> 32) == 2ull) break;
                p--;
            }
            g_state[b] = (2ull << 32) | (unsigned)(excl + total);
            s_excl = excl;
        }
    }
    __syncthreads();

    int base = s_excl + ((wid > 0) ? ws[wid - 1] : 0) + (x - s);
    if (idx < N4) {
        int i = idx * 4;
        int e0 = base, e1 = e0 + v.x, e2 = e1 + v.y, e3 = e2 + v.z;
        g_rowptr[i + 0] = e0; g_cursor[i + 0] = e0;
        g_rowptr[i + 1] = e1; g_cursor[i + 1] = e1;
        g_rowptr[i + 2] = e2; g_cursor[i + 2] = e2;
        g_rowptr[i + 3] = e3; g_cursor[i + 3] = e3;
        g_dis[i + 0] = (v.x > 0) ? rsqrtf((float)v.x) : 0.0f;
        g_dis[i + 1] = (v.y > 0) ? rsqrtf((float)v.y) : 0.0f;
        g_dis[i + 2] = (v.z > 0) ? rsqrtf((float)v.z) : 0.0f;
        g_dis[i + 3] = (v.w > 0) ? rsqrtf((float)v.w) : 0.0f;
    }
    if (b == 0 && t == 0) g_rowptr[N_NODES] = n_edges;
}

__global__ void scatter_init_kernel(const int* __restrict__ h, const int* __restrict__ t,
                                    int n,
                                    const float* __restrict__ u, const float* __restrict__ it,
                                    float* __restrict__ embA, float* __restrict__ out,
                                    __half* __restrict__ S) {
    const int stride = gridDim.x * blockDim.x;
    const int tid0 = blockIdx.x * blockDim.x + threadIdx.x;
    const int total4 = N_NODES * EMB / 4;
    const int ub4 = N_USERS * EMB / 4;
    const float third = 1.0f / 3.0f;
    for (int i = tid0; i < total4; i += stride) {
        float4 v = (i < ub4) ? ((const float4*)u)[i] : ((const float4*)it)[i - ub4];
        ((float4*)embA)[i] = v;
        ((float4*)out)[i] = make_float4(v.x * third, v.y * third, v.z * third, v.w * third);
        float d = g_dis[i >> 4];
        ((__half2*)S)[i * 2 + 0] = __floats2half2_rn(v.x * d, v.y * d);
        ((__half2*)S)[i * 2 + 1] = __floats2half2_rn(v.z * d, v.w * d);
    }
    for (int i = tid0; i < n; i += stride) {
        int hh = h[i];
        int pos = atomicAdd(&g_cursor[hh], 1);
        g_ecol[pos] = t[i];
    }
}

// ---------------- SPMM: warp/node, fp16 rows, 8 lanes/row, 4 edges/step, pipelined ----------------
__global__ __launch_bounds__(256) void spmm_kernel(const __half* __restrict__ S,
                                                   float* __restrict__ xout) {
    const int lane = threadIdx.x & 31;
    const int grp = lane >> 3;
    const int q = lane & 7;
    const int n = (blockIdx.x << 3) + (threadIdx.x >> 5);
    if (n >= N_NODES) return;
    const int beg = g_rowptr[n], end = g_rowptr[n + 1];
    const uint4* S4 = (const uint4*)S;

    unsigned long long a0 = 0ull, a1 = 0ull, a2 = 0ull, a3 = 0ull;
    const unsigned long long one2 = 0x3f8000003f800000ull;
    int j = beg;
    const int nq = (end - beg) >> 2;

    if (nq > 0) {
        int c = g_ecol[j + grp];
        uint4 v = S4[(size_t)c * 8 + q];
        for (int b = 1; b < nq; b++) {
            j += 4;
            int d = g_ecol[j + grp];
            uint4 w = S4[(size_t)d * 8 + q];
            a0 = fma2(h2f2(v.x), one2, a0);
            a1 = fma2(h2f2(v.y), one2, a1);
            a2 = fma2(h2f2(v.z), one2, a2);
            a3 = fma2(h2f2(v.w), one2, a3);
            v = w;
        }
        a0 = fma2(h2f2(v.x), one2, a0);
        a1 = fma2(h2f2(v.y), one2, a1);
        a2 = fma2(h2f2(v.z), one2, a2);
        a3 = fma2(h2f2(v.w), one2, a3);
        j += 4;
    }

    if (j + grp < end) {
        int c = g_ecol[j + grp];
        uint4 v = S4[(size_t)c * 8 + q];
        a0 = fma2(h2f2(v.x), one2, a0);
        a1 = fma2(h2f2(v.y), one2, a1);
        a2 = fma2(h2f2(v.z), one2, a2);
        a3 = fma2(h2f2(v.w), one2, a3);
    }

    float2 f0 = upk(a0), f1 = upk(a1), f2 = upk(a2), f3 = upk(a3);
    #pragma unroll
    for (int o = 8; o <= 16; o <<= 1) {
        f0.x += __shfl_xor_sync(0xffffffffu, f0.x, o);
        f0.y += __shfl_xor_sync(0xffffffffu, f0.y, o);
        f1.x += __shfl_xor_sync(0xffffffffu, f1.x, o);
        f1.y += __shfl_xor_sync(0xffffffffu, f1.y, o);
        f2.x += __shfl_xor_sync(0xffffffffu, f2.x, o);
        f2.y += __shfl_xor_sync(0xffffffffu, f2.y, o);
        f3.x += __shfl_xor_sync(0xffffffffu, f3.x, o);
        f3.y += __shfl_xor_sync(0xffffffffu, f3.y, o);
    }

    if (grp == 0) {
        float dn = g_dis[n];
        float* row = xout + (size_t)n * EMB + q * 8;
        *(float4*)(row)     = make_float4(f0.x * dn, f0.y * dn, f1.x * dn, f1.y * dn);
        *(float4*)(row + 4) = make_float4(f2.x * dn, f2.y * dn, f3.x * dn, f3.y * dn);
    }
}

// ================ wmma bf16 hi/lo intent kernel =================
// phase1: L = X[128,64] @ W[64,128]   (3 passes: XhWh + XhWl + XlWh)
// softmax rows -> P (bf16 hi/lo)
// phase2: Y = P[128,128] @ W^T        (W smem reused as col_major fragment)

#define XLD 72    // bf16 elems per row (64 + 8 pad)
#define WLD 136   // bf16 elems per row (128 + 8 pad)
#define PLD 136
#define LLD 132   // fp32 logits ld
#define YLD 68    // fp32 Y ld

#define OFF_WHI 0
#define OFF_WLO 17408                  // 64*136*2
#define OFF_P   34816                  // Phi here (X aliased in same region)
#define OFF_XHI OFF_P                  // 128*72*2 = 18432
#define OFF_XLO (OFF_P + 18432)
#define OFF_PLO (OFF_P + 34816)        // 128*136*2
#define OFF_L   (OFF_P + 69632)        // fp32 logits 128*132*4 = 67584
#define SMEM_TC (OFF_L + 67584)        // 172032 B

__device__ __forceinline__ void f2bf2(float x, __nv_bfloat16& hi, __nv_bfloat16& lo) {
    hi = __float2bfloat16(x);
    lo = __float2bfloat16(x - __bfloat162float(hi));
}

__global__ __launch_bounds__(256, 1) void intent_tc_kernel(
    const float* __restrict__ xin, const float* __restrict__ W,
    float* __restrict__ xio, float* __restrict__ out,
    __half* __restrict__ Sout) {
    extern __shared__ char smem[];
    __nv_bfloat16* sWhi = (__nv_bfloat16*)(smem + OFF_WHI);
    __nv_bfloat16* sWlo = (__nv_bfloat16*)(smem + OFF_WLO);
    __nv_bfloat16* sXhi = (__nv_bfloat16*)(smem + OFF_XHI);
    __nv_bfloat16* sXlo = (__nv_bfloat16*)(smem + OFF_XLO);
    __nv_bfloat16* sPhi = (__nv_bfloat16*)(smem + OFF_P);
    __nv_bfloat16* sPlo = (__nv_bfloat16*)(smem + OFF_PLO);
    float* sL = (float*)(smem + OFF_L);

    const int tid = threadIdx.x;
    const int w = tid >> 5;
    const int node0 = blockIdx.x * 128;

    // ---- load W (64x128) -> bf16 hi/lo ----
    for (int i4 = tid; i4 < 64 * 128 / 4; i4 += 256) {
        int d = i4 >> 5, j4 = (i4 & 31) << 2;
        float4 v = *(const float4*)(W + d * 128 + j4);
        __nv_bfloat16 h0, l0, h1, l1, h2, l2, h3, l3;
        f2bf2(v.x, h0, l0); f2bf2(v.y, h1, l1);
        f2bf2(v.z, h2, l2); f2bf2(v.w, h3, l3);
        __nv_bfloat16* ph = sWhi + d * WLD + j4;
        __nv_bfloat16* pl = sWlo + d * WLD + j4;
        ph[0] = h0; ph[1] = h1; ph[2] = h2; ph[3] = h3;
        pl[0] = l0; pl[1] = l1; pl[2] = l2; pl[3] = l3;
    }
    // ---- load X tile (128x64) -> bf16 hi/lo ----
    for (int i4 = tid; i4 < 128 * 64 / 4; i4 += 256) {
        int m = i4 >> 4, k4 = (i4 & 15) << 2;
        int nd = node0 + m;
        float4 v = (nd < N_NODES) ? *(const float4*)(xin + (size_t)nd * EMB + k4)
                                  : make_float4(0.f, 0.f, 0.f, 0.f);
        __nv_bfloat16 h0, l0, h1, l1, h2, l2, h3, l3;
        f2bf2(v.x, h0, l0); f2bf2(v.y, h1, l1);
        f2bf2(v.z, h2, l2); f2bf2(v.w, h3, l3);
        __nv_bfloat16* ph = sXhi + m * XLD + k4;
        __nv_bfloat16* pl = sXlo + m * XLD + k4;
        ph[0] = h0; ph[1] = h1; ph[2] = h2; ph[3] = h3;
        pl[0] = l0; pl[1] = l1; pl[2] = l2; pl[3] = l3;
    }
    __syncthreads();

    // ---- phase 1: warp w computes rows [16w,16w+16) x 128 cols ----
    {
        wmma::fragment<wmma::accumulator, 16, 16, 16, float> acc[8];
        #pragma unroll
        for (int cb = 0; cb < 8; cb++) wmma::fill_fragment(acc[cb], 0.0f);
        #pragma unroll
        for (int kf = 0; kf < 4; kf++) {
            wmma::fragment<wmma::matrix_a, 16, 16, 16, __nv_bfloat16, wmma::row_major> ahi, alo;
            wmma::load_matrix_sync(ahi, sXhi + w * 16 * XLD + kf * 16, XLD);
            wmma::load_matrix_sync(alo, sXlo + w * 16 * XLD + kf * 16, XLD);
            #pragma unroll
            for (int cb = 0; cb < 8; cb++) {
                wmma::fragment<wmma::matrix_b, 16, 16, 16, __nv_bfloat16, wmma::row_major> bhi, blo;
                wmma::load_matrix_sync(bhi, sWhi + kf * 16 * WLD + cb * 16, WLD);
                wmma::load_matrix_sync(blo, sWlo + kf * 16 * WLD + cb * 16, WLD);
                wmma::mma_sync(acc[cb], ahi, bhi, acc[cb]);
                wmma::mma_sync(acc[cb], ahi, blo, acc[cb]);
                wmma::mma_sync(acc[cb], alo, bhi, acc[cb]);
            }
        }
        #pragma unroll
        for (int cb = 0; cb < 8; cb++)
            wmma::store_matrix_sync(sL + w * 16 * LLD + cb * 16, acc[cb], LLD, wmma::mem_row_major);
    }
    __syncthreads();

    // ---- softmax: 2 threads per row (64 cols each), then store P bf16 hi/lo ----
    {
        const int row = tid >> 1, half = tid & 1;
        float* base = sL + row * LLD + half * 64;
        float mx = base[0];
        #pragma unroll 16
        for (int c = 1; c < 64; c++) mx = fmaxf(mx, base[c]);
        mx = fmaxf(mx, __shfl_xor_sync(0xffffffffu, mx, 1));
        float s = 0.f;
        #pragma unroll 16
        for (int c = 0; c < 64; c++) {
            float e = __expf(base[c] - mx);
            base[c] = e;
            s += e;
        }
        s += __shfl_xor_sync(0xffffffffu, s, 1);
        float inv = 1.0f / s;
        __nv_bfloat16* ph = sPhi + row * PLD + half * 64;
        __nv_bfloat16* pl = sPlo + row * PLD + half * 64;
        #pragma unroll 16
        for (int c = 0; c < 64; c++) {
            __nv_bfloat16 hi, lo;
            f2bf2(base[c] * inv, hi, lo);
            ph[c] = hi;
            pl[c] = lo;
        }
    }
    __syncthreads();

    // ---- phase 2: Y[16w:16w+16, 0:64] = P @ W^T  (W read as col_major) ----
    {
        wmma::fragment<wmma::accumulator, 16, 16, 16, float> acc[4];
        #pragma unroll
        for (int cb = 0; cb < 4; cb++) wmma::fill_fragment(acc[cb], 0.0f);
        #pragma unroll
        for (int kf = 0; kf < 8; kf++) {
            wmma::fragment<wmma::matrix_a, 16, 16, 16, __nv_bfloat16, wmma::row_major> ahi, alo;
            wmma::load_matrix_sync(ahi, sPhi + w * 16 * PLD + kf * 16, PLD);
            wmma::load_matrix_sync(alo, sPlo + w * 16 * PLD + kf * 16, PLD);
            #pragma unroll
            for (int cb = 0; cb < 4; cb++) {
                wmma::fragment<wmma::matrix_b, 16, 16, 16, __nv_bfloat16, wmma::col_major> bhi, blo;
                wmma::load_matrix_sync(bhi, sWhi + cb * 16 * WLD + kf * 16, WLD);
                wmma::load_matrix_sync(blo, sWlo + cb * 16 * WLD + kf * 16, WLD);
                wmma::mma_sync(acc[cb], ahi, bhi, acc[cb]);
                wmma::mma_sync(acc[cb], ahi, blo, acc[cb]);
                wmma::mma_sync(acc[cb], alo, bhi, acc[cb]);
            }
        }
        #pragma unroll
        for (int cb = 0; cb < 4; cb++)
            wmma::store_matrix_sync(sL + w * 16 * YLD + cb * 16, acc[cb], YLD, wmma::mem_row_major);
    }
    __syncthreads();

    // ---- epilogue: y = gnn + intent; xio = y; out += y/3; optional S = half(dis*y) ----
    {
        const float third = 1.0f / 3.0f;
        for (int i4 = tid; i4 < 128 * 16; i4 += 256) {
            int m = i4 >> 4, c4 = (i4 & 15) << 2;
            int nd = node0 + m;
            if (nd >= N_NODES) continue;
            size_t idx = (size_t)nd * EMB + c4;
            float* yp = sL + m * YLD + c4;
            float4 g = *(const float4*)(xio + idx);
            float4 y = make_float4(yp[0] + g.x, yp[1] + g.y, yp[2] + g.z, yp[3] + g.w);
            *(float4*)(xio + idx) = y;
            float4 o = *(const float4*)(out + idx);
            o.x += y.x * third; o.y += y.y * third;
            o.z += y.z * third; o.w += y.w * third;
            *(float4*)(out + idx) = o;
            if (Sout) {
                float d = g_dis[nd];
                ((__half2*)(Sout + idx))[0] = __floats2half2_rn(y.x * d, y.y * d);
                ((__half2*)(Sout + idx))[1] = __floats2half2_rn(y.z * d, y.w * d);
            }
        }
    }
}

// ---------------- launch ----------------
extern "C" void kernel_launch(void* const* d_in, const int* in_sizes, int n_in,
                              void* d_out, int out_size) {
    const float* user = (const float*)d_in[0];
    const float* item = (const float*)d_in[1];
    const float* W    = (const float*)d_in[2];
    const int*   hix  = (const int*)d_in[3];
    const int*   tix  = (const int*)d_in[4];
    const int n_edges = in_sizes[3];
    float* out = (float*)d_out;

    cudaFuncSetAttribute(intent_tc_kernel,
                         cudaFuncAttributeMaxDynamicSharedMemorySize, SMEM_TC);

    float *A, *B;
    __half* S;
    void *degp, *statep;
    cudaGetSymbolAddress((void**)&A, g_embA);
    cudaGetSymbolAddress((void**)&B, g_embB);
    cudaGetSymbolAddress((void**)&S, g_embS);
    cudaGetSymbolAddress(&degp, g_deg);
    cudaGetSymbolAddress(&statep, g_state);

    const int TB = 256;
    cudaMemsetAsync(degp, 0, N_NODES * sizeof(int));
    cudaMemsetAsync(statep, 0, NBLK * sizeof(unsigned long long));

    hist_kernel<<<4096, TB>>>(hix, n_edges);                               // kernel 1
    scan_kernel<<<NBLK, 1024>>>(n_edges);                                  // kernel 2
    scatter_init_kernel<<<4096, TB>>>(hix, tix, n_edges, user, item, A, out, S); // kernel 3

    const int spmm_blocks = (N_NODES + 7) / 8;
    const int tile_blocks = (N_NODES + 127) / 128;

    // layer 0
    spmm_kernel<<<spmm_blocks, TB>>>(S, B);                                // kernel 4 (profiled)
    intent_tc_kernel<<<tile_blocks, TB, SMEM_TC>>>(A, W, B, out, S);
    // layer 1
    spmm_kernel<<<spmm_blocks, TB>>>(S, A);
    intent_tc_kernel<<<tile_blocks, TB, SMEM_TC>>>(B, W, A, out, nullptr);
}

// round 11
// speedup vs baseline: 1.5379x; 1.5379x over previous
#include <cuda_runtime.h>
#include <cuda_fp16.h>
#include <math.h>
#include <cstdint>

#define N_USERS 100000
#define N_ITEMS 50000
#define N_NODES 150000
#define EMB 64
#define NINT 128
#define MAX_EDGES 4000000

#define N4 ((N_NODES + 3) / 4)
#define NBLK ((N4 + 1023) / 1024)

// ---------------- static device scratch ----------------
__device__ int    g_deg[N_NODES];
__device__ float  g_dis[N_NODES];
__device__ int    g_rowptr[N_NODES + 1];
__device__ int    g_cursor[N_NODES];
__device__ int    g_ecol[MAX_EDGES];
__device__ volatile unsigned long long g_state[NBLK];
__device__ float  g_embA[(size_t)N_NODES * EMB];
__device__ float  g_embB[(size_t)N_NODES * EMB];
__device__ __half g_embS[(size_t)N_NODES * EMB];   // dis-scaled spmm input (fp16)

// ---------------- packed fp32x2 helpers (spmm) ----------------
__device__ __forceinline__ unsigned long long fma2(unsigned long long a,
                                                   unsigned long long b,
                                                   unsigned long long c) {
    unsigned long long d;
    asm("fma.rn.f32x2 %0, %1, %2, %3;" : "=l"(d) : "l"(a), "l"(b), "l"(c));
    return d;
}
__device__ __forceinline__ unsigned long long pk2(float x, float y) {
    unsigned long long r;
    asm("mov.b64 %0, {%1, %2};" : "=l"(r) : "f"(x), "f"(y));
    return r;
}
__device__ __forceinline__ float2 upk(unsigned long long v) {
    float2 f;
    asm("mov.b64 {%0, %1}, %2;" : "=f"(f.x), "=f"(f.y) : "l"(v));
    return f;
}
__device__ __forceinline__ unsigned long long h2f2(unsigned int h) {
    float2 f = __half22float2(*(const __half2*)&h);
    return pk2(f.x, f.y);
}

// ---------------- precompute ----------------
__global__ void hist_kernel(const int* __restrict__ h, int n) {
    int stride = gridDim.x * blockDim.x;
    for (int i = blockIdx.x * blockDim.x + threadIdx.x; i < n; i += stride)
        atomicAdd(&g_deg[h[i]], 1);
}

__global__ __launch_bounds__(1024) void scan_kernel(int n_edges) {
    __shared__ int ws[32];
    __shared__ int s_excl;
    const int t = threadIdx.x, b = blockIdx.x;
    const int lane = t & 31, wid = t >> 5;
    const int idx = b * 1024 + t;
    int4 v = (idx < N4) ? ((const int4*)g_deg)[idx] : make_int4(0, 0, 0, 0);
    int s = v.x + v.y + v.z + v.w;
    int x = s;
    #pragma unroll
    for (int o = 1; o < 32; o <<= 1) {
        int y = __shfl_up_sync(0xffffffffu, x, o);
        if (lane >= o) x += y;
    }
    if (lane == 31) ws[wid] = x;
    __syncthreads();
    if (wid == 0) {
        int z = ws[lane];
        #pragma unroll
        for (int o = 1; o < 32; o <<= 1) {
            int y = __shfl_up_sync(0xffffffffu, z, o);
            if (lane >= o) z += y;
        }
        ws[lane] = z;
    }
    __syncthreads();
    const int total = ws[31];

    if (t == 0) {
        if (b == 0) {
            g_state[0] = (2ull << 32) | (unsigned)total;
            s_excl = 0;
        } else {
            g_state[b] = (1ull << 32) | (unsigned)total;
            int excl = 0;
            int p = b - 1;
            while (true) {
                unsigned long long st;
                do { st = g_state[p]; } while ((st >> 32) == 0ull);
                excl += (int)(unsigned)st;
                if ((st >> 32) == 2ull) break;
                p--;
            }
            g_state[b] = (2ull << 32) | (unsigned)(excl + total);
            s_excl = excl;
        }
    }
    __syncthreads();

    int base = s_excl + ((wid > 0) ? ws[wid - 1] : 0) + (x - s);
    if (idx < N4) {
        int i = idx * 4;
        int e0 = base, e1 = e0 + v.x, e2 = e1 + v.y, e3 = e2 + v.z;
        g_rowptr[i + 0] = e0; g_cursor[i + 0] = e0;
        g_rowptr[i + 1] = e1; g_cursor[i + 1] = e1;
        g_rowptr[i + 2] = e2; g_cursor[i + 2] = e2;
        g_rowptr[i + 3] = e3; g_cursor[i + 3] = e3;
        g_dis[i + 0] = (v.x > 0) ? rsqrtf((float)v.x) : 0.0f;
        g_dis[i + 1] = (v.y > 0) ? rsqrtf((float)v.y) : 0.0f;
        g_dis[i + 2] = (v.z > 0) ? rsqrtf((float)v.z) : 0.0f;
        g_dis[i + 3] = (v.w > 0) ? rsqrtf((float)v.w) : 0.0f;
    }
    if (b == 0 && t == 0) g_rowptr[N_NODES] = n_edges;
}

__global__ void scatter_init_kernel(const int* __restrict__ h, const int* __restrict__ t,
                                    int n,
                                    const float* __restrict__ u, const float* __restrict__ it,
                                    float* __restrict__ embA, float* __restrict__ out,
                                    __half* __restrict__ S) {
    const int stride = gridDim.x * blockDim.x;
    const int tid0 = blockIdx.x * blockDim.x + threadIdx.x;
    const int total4 = N_NODES * EMB / 4;
    const int ub4 = N_USERS * EMB / 4;
    const float third = 1.0f / 3.0f;
    for (int i = tid0; i < total4; i += stride) {
        float4 v = (i < ub4) ? ((const float4*)u)[i] : ((const float4*)it)[i - ub4];
        ((float4*)embA)[i] = v;
        ((float4*)out)[i] = make_float4(v.x * third, v.y * third, v.z * third, v.w * third);
        float d = g_dis[i >> 4];
        ((__half2*)S)[i * 2 + 0] = __floats2half2_rn(v.x * d, v.y * d);
        ((__half2*)S)[i * 2 + 1] = __floats2half2_rn(v.z * d, v.w * d);
    }
    for (int i = tid0; i < n; i += stride) {
        int hh = h[i];
        int pos = atomicAdd(&g_cursor[hh], 1);
        g_ecol[pos] = t[i];
    }
}

// ---------------- SPMM: warp/node, fp16 rows, 8 lanes/row, pipelined ----------------
__global__ __launch_bounds__(256) void spmm_kernel(const __half* __restrict__ S,
                                                   float* __restrict__ xout) {
    const int lane = threadIdx.x & 31;
    const int grp = lane >> 3;
    const int q = lane & 7;
    const int n = (blockIdx.x << 3) + (threadIdx.x >> 5);
    if (n >= N_NODES) return;
    const int beg = g_rowptr[n], end = g_rowptr[n + 1];
    const uint4* S4 = (const uint4*)S;

    unsigned long long a0 = 0ull, a1 = 0ull, a2 = 0ull, a3 = 0ull;
    const unsigned long long one2 = 0x3f8000003f800000ull;
    int j = beg;
    const int nq = (end - beg) >> 2;

    if (nq > 0) {
        int c = g_ecol[j + grp];
        uint4 v = S4[(size_t)c * 8 + q];
        for (int b = 1; b < nq; b++) {
            j += 4;
            int d = g_ecol[j + grp];
            uint4 w = S4[(size_t)d * 8 + q];
            a0 = fma2(h2f2(v.x), one2, a0);
            a1 = fma2(h2f2(v.y), one2, a1);
            a2 = fma2(h2f2(v.z), one2, a2);
            a3 = fma2(h2f2(v.w), one2, a3);
            v = w;
        }
        a0 = fma2(h2f2(v.x), one2, a0);
        a1 = fma2(h2f2(v.y), one2, a1);
        a2 = fma2(h2f2(v.z), one2, a2);
        a3 = fma2(h2f2(v.w), one2, a3);
        j += 4;
    }

    if (j + grp < end) {
        int c = g_ecol[j + grp];
        uint4 v = S4[(size_t)c * 8 + q];
        a0 = fma2(h2f2(v.x), one2, a0);
        a1 = fma2(h2f2(v.y), one2, a1);
        a2 = fma2(h2f2(v.z), one2, a2);
        a3 = fma2(h2f2(v.w), one2, a3);
    }

    float2 f0 = upk(a0), f1 = upk(a1), f2 = upk(a2), f3 = upk(a3);
    #pragma unroll
    for (int o = 8; o <= 16; o <<= 1) {
        f0.x += __shfl_xor_sync(0xffffffffu, f0.x, o);
        f0.y += __shfl_xor_sync(0xffffffffu, f0.y, o);
        f1.x += __shfl_xor_sync(0xffffffffu, f1.x, o);
        f1.y += __shfl_xor_sync(0xffffffffu, f1.y, o);
        f2.x += __shfl_xor_sync(0xffffffffu, f2.x, o);
        f2.y += __shfl_xor_sync(0xffffffffu, f2.y, o);
        f3.x += __shfl_xor_sync(0xffffffffu, f3.x, o);
        f3.y += __shfl_xor_sync(0xffffffffu, f3.y, o);
    }

    if (grp == 0) {
        float dn = g_dis[n];
        float* row = xout + (size_t)n * EMB + q * 8;
        *(float4*)(row)     = make_float4(f0.x * dn, f0.y * dn, f1.x * dn, f1.y * dn);
        *(float4*)(row + 4) = make_float4(f2.x * dn, f2.y * dn, f3.x * dn, f3.y * dn);
    }
}

// ================ mma.sync fp16 intent kernel ================
// phase1: L[128m,128j] = X @ W       (A = X row, B = W^T rows in smem)
// softmax in registers (quad shuffles), accs repacked directly as phase2 A frags
// phase2: Y[128m,64d] = P @ W^T      (B = W rows in smem)

#define OFF_WT 0               // W^T [128j][72d] fp16 = 18432 B
#define OFF_W2 18432           // W   [64d][136j] fp16 = 17408 B
#define OFF_X  35840           // X   [128m][72d] fp16 = 18432 B
#define SMEM_MMA 54272
#define WTLDB 144              // 72 halves * 2
#define W2LDB 272              // 136 halves * 2
#define XLDB  144

__device__ __forceinline__ uint32_t pack_h2(float x, float y) {
    __half2 h = __floats2half2_rn(x, y);
    return *(uint32_t*)&h;
}

__device__ __forceinline__ void ldmx4(uint32_t addr, uint32_t& r0, uint32_t& r1,
                                      uint32_t& r2, uint32_t& r3) {
    asm volatile("ldmatrix.sync.aligned.m8n8.x4.shared.b16 {%0,%1,%2,%3}, [%4];"
                 : "=r"(r0), "=r"(r1), "=r"(r2), "=r"(r3) : "r"(addr));
}
__device__ __forceinline__ void ldmx2(uint32_t addr, uint32_t& r0, uint32_t& r1) {
    asm volatile("ldmatrix.sync.aligned.m8n8.x2.shared.b16 {%0,%1}, [%2];"
                 : "=r"(r0), "=r"(r1) : "r"(addr));
}
__device__ __forceinline__ void mma16816(float& c0, float& c1, float& c2, float& c3,
                                         uint32_t a0, uint32_t a1, uint32_t a2, uint32_t a3,
                                         uint32_t b0, uint32_t b1) {
    asm volatile("mma.sync.aligned.m16n8k16.row.col.f32.f16.f16.f32 "
                 "{%0,%1,%2,%3}, {%4,%5,%6,%7}, {%8,%9}, {%0,%1,%2,%3};"
                 : "+f"(c0), "+f"(c1), "+f"(c2), "+f"(c3)
                 : "r"(a0), "r"(a1), "r"(a2), "r"(a3), "r"(b0), "r"(b1));
}

__global__ __launch_bounds__(256, 2) void intent_mma_kernel(
    const float* __restrict__ xin, const float* __restrict__ W,
    float* __restrict__ xio, float* __restrict__ out,
    __half* __restrict__ Sout) {
    extern __shared__ char smem[];
    __half* hWT = (__half*)(smem + OFF_WT);
    __half* hW2 = (__half*)(smem + OFF_W2);
    __half* hX  = (__half*)(smem + OFF_X);
    const uint32_t sb = (uint32_t)__cvta_generic_to_shared(smem);

    const int tid = threadIdx.x;
    const int w = tid >> 5, lane = tid & 31;
    const int node0 = blockIdx.x * 128;

    // ---- stage W^T (for phase1 B), W (for phase2 B), X — all fp16 ----
    for (int i = tid; i < 64 * 128; i += 256) {
        int d = i >> 7, j = i & 127;
        hWT[j * 72 + d] = __float2half(W[i]);
    }
    for (int i2 = tid; i2 < 64 * 64; i2 += 256) {
        int d = i2 >> 6, j2 = i2 & 63;
        float2 v = *(const float2*)(W + d * 128 + j2 * 2);
        ((__half2*)hW2)[d * 68 + j2] = __floats2half2_rn(v.x, v.y);
    }
    for (int i2 = tid; i2 < 128 * 32; i2 += 256) {
        int m = i2 >> 5, d2 = i2 & 31;
        int nd = node0 + m;
        float2 v = (nd < N_NODES) ? *(const float2*)(xin + (size_t)nd * EMB + d2 * 2)
                                  : make_float2(0.f, 0.f);
        ((__half2*)hX)[m * 36 + d2] = __floats2half2_rn(v.x, v.y);
    }
    __syncthreads();

    // ---- phase 1: warp w owns rows m0..m0+16; logits acc[16 n-tiles][4] ----
    const int m0 = w * 16;
    float acc[16][4];
    #pragma unroll
    for (int n = 0; n < 16; n++) {
        acc[n][0] = 0.f; acc[n][1] = 0.f; acc[n][2] = 0.f; acc[n][3] = 0.f;
    }

    // A fragment addresses (X): row = m0 + (lane&7) + 8*((lane>>3)&1), colblk = lane>>4
    const uint32_t xrow = (uint32_t)(m0 + (lane & 7) + 8 * ((lane >> 3) & 1));
    const uint32_t xaddr0 = sb + OFF_X + xrow * XLDB + (uint32_t)(lane >> 4) * 16;
    // B fragment addresses (W^T): row j = n*8 + (lane&7), matsel = (lane>>3)&1
    const uint32_t brow_in = (uint32_t)(lane & 7);
    const uint32_t bmat = (uint32_t)((lane >> 3) & 1) * 16;

    #pragma unroll
    for (int kf = 0; kf < 4; kf++) {
        uint32_t a0, a1, a2, a3;
        ldmx4(xaddr0 + kf * 32, a0, a1, a2, a3);
        #pragma unroll
        for (int n = 0; n < 16; n++) {
            uint32_t b0, b1;
            uint32_t baddr = sb + OFF_WT + (n * 8 + brow_in) * WTLDB + kf * 32 + bmat;
            ldmx2(baddr, b0, b1);
            mma16816(acc[n][0], acc[n][1], acc[n][2], acc[n][3], a0, a1, a2, a3, b0, b1);
        }
    }

    // ---- softmax in registers: rows r_lo = m0 + lane/4, r_hi = +8 ----
    float mx_lo = -1e30f, mx_hi = -1e30f;
    #pragma unroll
    for (int n = 0; n < 16; n++) {
        mx_lo = fmaxf(mx_lo, fmaxf(acc[n][0], acc[n][1]));
        mx_hi = fmaxf(mx_hi, fmaxf(acc[n][2], acc[n][3]));
    }
    mx_lo = fmaxf(mx_lo, __shfl_xor_sync(0xffffffffu, mx_lo, 1));
    mx_lo = fmaxf(mx_lo, __shfl_xor_sync(0xffffffffu, mx_lo, 2));
    mx_hi = fmaxf(mx_hi, __shfl_xor_sync(0xffffffffu, mx_hi, 1));
    mx_hi = fmaxf(mx_hi, __shfl_xor_sync(0xffffffffu, mx_hi, 2));
    float s_lo = 0.f, s_hi = 0.f;
    #pragma unroll
    for (int n = 0; n < 16; n++) {
        acc[n][0] = __expf(acc[n][0] - mx_lo); s_lo += acc[n][0];
        acc[n][1] = __expf(acc[n][1] - mx_lo); s_lo += acc[n][1];
        acc[n][2] = __expf(acc[n][2] - mx_hi); s_hi += acc[n][2];
        acc[n][3] = __expf(acc[n][3] - mx_hi); s_hi += acc[n][3];
    }
    s_lo += __shfl_xor_sync(0xffffffffu, s_lo, 1);
    s_lo += __shfl_xor_sync(0xffffffffu, s_lo, 2);
    s_hi += __shfl_xor_sync(0xffffffffu, s_hi, 1);
    s_hi += __shfl_xor_sync(0xffffffffu, s_hi, 2);
    const float inv_lo = 1.0f / s_lo, inv_hi = 1.0f / s_hi;

    // ---- repack scaled accs directly as phase2 A fragments (P, fp16) ----
    uint32_t A2[8][4];
    #pragma unroll
    for (int kf2 = 0; kf2 < 8; kf2++) {
        A2[kf2][0] = pack_h2(acc[2 * kf2][0] * inv_lo,     acc[2 * kf2][1] * inv_lo);
        A2[kf2][1] = pack_h2(acc[2 * kf2][2] * inv_hi,     acc[2 * kf2][3] * inv_hi);
        A2[kf2][2] = pack_h2(acc[2 * kf2 + 1][0] * inv_lo, acc[2 * kf2 + 1][1] * inv_lo);
        A2[kf2][3] = pack_h2(acc[2 * kf2 + 1][2] * inv_hi, acc[2 * kf2 + 1][3] * inv_hi);
    }

    // ---- phase 2: Y[m0:m0+16, 64] = P @ W^T; B rows = W[d][j] ----
    float acc2[8][4];
    #pragma unroll
    for (int n2 = 0; n2 < 8; n2++) {
        acc2[n2][0] = 0.f; acc2[n2][1] = 0.f; acc2[n2][2] = 0.f; acc2[n2][3] = 0.f;
    }
    #pragma unroll
    for (int kf2 = 0; kf2 < 8; kf2++) {
        #pragma unroll
        for (int n2 = 0; n2 < 8; n2++) {
            uint32_t b0, b1;
            uint32_t baddr = sb + OFF_W2 + (n2 * 8 + brow_in) * W2LDB + kf2 * 32 + bmat;
            ldmx2(baddr, b0, b1);
            mma16816(acc2[n2][0], acc2[n2][1], acc2[n2][2], acc2[n2][3],
                     A2[kf2][0], A2[kf2][1], A2[kf2][2], A2[kf2][3], b0, b1);
        }
    }

    // ---- fragment-direct epilogue ----
    const float third = 1.0f / 3.0f;
    const int r_lo = node0 + m0 + (lane >> 2);
    const int r_hi = r_lo + 8;
    const int q2 = (lane & 3) * 2;
    const float d_lo = (Sout && r_lo < N_NODES) ? g_dis[r_lo] : 0.0f;
    const float d_hi = (Sout && r_hi < N_NODES) ? g_dis[r_hi] : 0.0f;
    #pragma unroll
    for (int n2 = 0; n2 < 8; n2++) {
        int dcol = n2 * 8 + q2;
        if (r_lo < N_NODES) {
            size_t idx = (size_t)r_lo * EMB + dcol;
            float2 g = *(const float2*)(xio + idx);
            float y0 = acc2[n2][0] + g.x, y1 = acc2[n2][1] + g.y;
            *(float2*)(xio + idx) = make_float2(y0, y1);
            float2 o = *(const float2*)(out + idx);
            *(float2*)(out + idx) = make_float2(o.x + y0 * third, o.y + y1 * third);
            if (Sout) *(__half2*)(Sout + idx) = __floats2half2_rn(y0 * d_lo, y1 * d_lo);
        }
        if (r_hi < N_NODES) {
            size_t idx = (size_t)r_hi * EMB + dcol;
            float2 g = *(const float2*)(xio + idx);
            float y0 = acc2[n2][2] + g.x, y1 = acc2[n2][3] + g.y;
            *(float2*)(xio + idx) = make_float2(y0, y1);
            float2 o = *(const float2*)(out + idx);
            *(float2*)(out + idx) = make_float2(o.x + y0 * third, o.y + y1 * third);
            if (Sout) *(__half2*)(Sout + idx) = __floats2half2_rn(y0 * d_hi, y1 * d_hi);
        }
    }
}

// ---------------- launch ----------------
extern "C" void kernel_launch(void* const* d_in, const int* in_sizes, int n_in,
                              void* d_out, int out_size) {
    const float* user = (const float*)d_in[0];
    const float* item = (const float*)d_in[1];
    const float* W    = (const float*)d_in[2];
    const int*   hix  = (const int*)d_in[3];
    const int*   tix  = (const int*)d_in[4];
    const int n_edges = in_sizes[3];
    float* out = (float*)d_out;

    cudaFuncSetAttribute(intent_mma_kernel,
                         cudaFuncAttributeMaxDynamicSharedMemorySize, SMEM_MMA);

    float *A, *B;
    __half* S;
    void *degp, *statep;
    cudaGetSymbolAddress((void**)&A, g_embA);
    cudaGetSymbolAddress((void**)&B, g_embB);
    cudaGetSymbolAddress((void**)&S, g_embS);
    cudaGetSymbolAddress(&degp, g_deg);
    cudaGetSymbolAddress(&statep, g_state);

    const int TB = 256;
    cudaMemsetAsync(degp, 0, N_NODES * sizeof(int));
    cudaMemsetAsync(statep, 0, NBLK * sizeof(unsigned long long));

    hist_kernel<<<4096, TB>>>(hix, n_edges);                               // kernel 1
    scan_kernel<<<NBLK, 1024>>>(n_edges);                                  // kernel 2
    scatter_init_kernel<<<4096, TB>>>(hix, tix, n_edges, user, item, A, out, S); // kernel 3

    const int spmm_blocks = (N_NODES + 7) / 8;
    const int tile_blocks = (N_NODES + 127) / 128;

    // layer 0
    spmm_kernel<<<spmm_blocks, TB>>>(S, B);                                // kernel 4 (profiled)
    intent_mma_kernel<<<tile_blocks, TB, SMEM_MMA>>>(A, W, B, out, S);
    // layer 1
    spmm_kernel<<<spmm_blocks, TB>>>(S, A);
    intent_mma_kernel<<<tile_blocks, TB, SMEM_MMA>>>(B, W, A, out, nullptr);
}